// round 12
// baseline (speedup 1.0000x reference)
#include <cuda_runtime.h>

// DEQSolver closed form: out[i] = sign(x[i]) * max(|x[i]| - lam, 0).
//
// FINAL (= R8, measured best at 9.184us): the Anderson-accelerated ISTA
// fixed point z = S_{rho*lam}((1-rho)z + rho*x) has exact closed form
// z* = S_lam(x), and the returned ista_step(z*, x) is S_lam(x) again —
// the entire 40-iteration solver collapses to one elementwise pass.
//
// Shape: one 256-bit load + one 256-bit store per thread (LDG.E.256/
// STG.E.256), 3072 blocks x 256 threads, L2::evict_last on both streams
// (50MB working set pinned in 126MB L2). Nine variants measured (MLP 1/4/6,
// wave-exact schedules, TMA bulk via SMEM, 128/256-bit widths, .nc datapath,
// eviction policies): all bracket 9.18-10.98us; this one is fastest. The
// ~9.2us is the environmental floor for a 50MB elementwise pass here — no
// pipe exceeds 34% utilization in ncu across any variant.

constexpr int THREADS = 256;

__global__ __launch_bounds__(THREADS) void deq_st_v8_el(
    const float* __restrict__ x,
    const float* __restrict__ lam_ptr,
    float* __restrict__ out,
    int nv8)
{
    int i = blockIdx.x * blockDim.x + threadIdx.x;
    if (i >= nv8) return;
    const float lam = *lam_ptr;

    const float* p = x   + (size_t)i * 8;
    float*       q = out + (size_t)i * 8;

    unsigned int b0, b1, b2, b3, b4, b5, b6, b7;
    asm volatile("ld.global.L2::evict_last.v8.b32 "
                 "{%0,%1,%2,%3,%4,%5,%6,%7}, [%8];"
                 : "=r"(b0), "=r"(b1), "=r"(b2), "=r"(b3),
                   "=r"(b4), "=r"(b5), "=r"(b6), "=r"(b7)
                 : "l"(p));

    float a0 = __int_as_float(b0), a1 = __int_as_float(b1);
    float a2 = __int_as_float(b2), a3 = __int_as_float(b3);
    float a4 = __int_as_float(b4), a5 = __int_as_float(b5);
    float a6 = __int_as_float(b6), a7 = __int_as_float(b7);

    float r0 = copysignf(fmaxf(fabsf(a0) - lam, 0.0f), a0);
    float r1 = copysignf(fmaxf(fabsf(a1) - lam, 0.0f), a1);
    float r2 = copysignf(fmaxf(fabsf(a2) - lam, 0.0f), a2);
    float r3 = copysignf(fmaxf(fabsf(a3) - lam, 0.0f), a3);
    float r4 = copysignf(fmaxf(fabsf(a4) - lam, 0.0f), a4);
    float r5 = copysignf(fmaxf(fabsf(a5) - lam, 0.0f), a5);
    float r6 = copysignf(fmaxf(fabsf(a6) - lam, 0.0f), a6);
    float r7 = copysignf(fmaxf(fabsf(a7) - lam, 0.0f), a7);

    asm volatile("st.global.L2::evict_last.v8.b32 "
                 "[%0], {%1,%2,%3,%4,%5,%6,%7,%8};"
                 :: "l"(q),
                    "r"(__float_as_uint(r0)), "r"(__float_as_uint(r1)),
                    "r"(__float_as_uint(r2)), "r"(__float_as_uint(r3)),
                    "r"(__float_as_uint(r4)), "r"(__float_as_uint(r5)),
                    "r"(__float_as_uint(r6)), "r"(__float_as_uint(r7))
                 : "memory");
}

// Scalar grid-stride fallback for any residual tail (unused: 6291456 % 8 == 0).
__global__ void deq_st_tail(const float* __restrict__ x,
                            const float* __restrict__ lam_ptr,
                            float* __restrict__ out, int start, int n) {
    const float lam = *lam_ptr;
    for (int i = start + blockIdx.x * blockDim.x + threadIdx.x; i < n;
         i += gridDim.x * blockDim.x) {
        float v = x[i];
        out[i] = copysignf(fmaxf(fabsf(v) - lam, 0.0f), v);
    }
}

extern "C" void kernel_launch(void* const* d_in, const int* in_sizes, int n_in,
                              void* d_out, int out_size) {
    const float* x0  = (const float*)d_in[0];
    const float* lam = (const float*)d_in[2];   // d_in[1]=rho irrelevant to fixed point
    float* out = (float*)d_out;

    int n   = in_sizes[0];
    int nv8 = n >> 3;                 // 786,432 for this shape
    int covered = nv8 << 3;

    if (nv8 > 0) {
        int blocks = (nv8 + THREADS - 1) / THREADS;   // 3072
        deq_st_v8_el<<<blocks, THREADS>>>(x0, lam, out, nv8);
    }
    if (covered < n) {
        deq_st_tail<<<148, THREADS>>>(x0, lam, out, covered, n);
    }
}

// round 13
// speedup vs baseline: 1.1000x; 1.1000x over previous
#include <cuda_runtime.h>

// DEQSolver closed form: out[i] = sign(x[i]) * max(|x[i]| - lam, 0).
//
// FINAL (R8 source, unchanged). Math: the Anderson-accelerated ISTA fixed
// point z = S_{rho*lam}((1-rho)z + rho*x) has exact closed form z* = S_lam(x)
// for rho in (0,1], and the returned ista_step(z*, x) equals S_lam(x) again —
// the entire 40-iteration solver collapses to one elementwise pass.
//
// Shape: one 256-bit load + one 256-bit store per thread (LDG.E.256 /
// STG.E.256), 3072 blocks x 256 threads, L2::evict_last on both streams.
// Nine variants measured (MLP 1/4/6, wave-exact schedules, TMA bulk via
// SMEM, 128/256-bit widths, .nc datapath, eviction policies); identical-
// binary re-runs show +-0.8us wall noise, making all sane shapes tie at the
// ~9.2-9.7us environmental floor (no pipe >34% in any ncu capture). This
// source holds the best measured wall (9.184us) and best ncu dur (9.25us).

constexpr int THREADS = 256;

__global__ __launch_bounds__(THREADS) void deq_st_v8_el(
    const float* __restrict__ x,
    const float* __restrict__ lam_ptr,
    float* __restrict__ out,
    int nv8)
{
    int i = blockIdx.x * blockDim.x + threadIdx.x;
    if (i >= nv8) return;
    const float lam = *lam_ptr;

    const float* p = x   + (size_t)i * 8;
    float*       q = out + (size_t)i * 8;

    unsigned int b0, b1, b2, b3, b4, b5, b6, b7;
    asm volatile("ld.global.L2::evict_last.v8.b32 "
                 "{%0,%1,%2,%3,%4,%5,%6,%7}, [%8];"
                 : "=r"(b0), "=r"(b1), "=r"(b2), "=r"(b3),
                   "=r"(b4), "=r"(b5), "=r"(b6), "=r"(b7)
                 : "l"(p));

    float a0 = __int_as_float(b0), a1 = __int_as_float(b1);
    float a2 = __int_as_float(b2), a3 = __int_as_float(b3);
    float a4 = __int_as_float(b4), a5 = __int_as_float(b5);
    float a6 = __int_as_float(b6), a7 = __int_as_float(b7);

    float r0 = copysignf(fmaxf(fabsf(a0) - lam, 0.0f), a0);
    float r1 = copysignf(fmaxf(fabsf(a1) - lam, 0.0f), a1);
    float r2 = copysignf(fmaxf(fabsf(a2) - lam, 0.0f), a2);
    float r3 = copysignf(fmaxf(fabsf(a3) - lam, 0.0f), a3);
    float r4 = copysignf(fmaxf(fabsf(a4) - lam, 0.0f), a4);
    float r5 = copysignf(fmaxf(fabsf(a5) - lam, 0.0f), a5);
    float r6 = copysignf(fmaxf(fabsf(a6) - lam, 0.0f), a6);
    float r7 = copysignf(fmaxf(fabsf(a7) - lam, 0.0f), a7);

    asm volatile("st.global.L2::evict_last.v8.b32 "
                 "[%0], {%1,%2,%3,%4,%5,%6,%7,%8};"
                 :: "l"(q),
                    "r"(__float_as_uint(r0)), "r"(__float_as_uint(r1)),
                    "r"(__float_as_uint(r2)), "r"(__float_as_uint(r3)),
                    "r"(__float_as_uint(r4)), "r"(__float_as_uint(r5)),
                    "r"(__float_as_uint(r6)), "r"(__float_as_uint(r7))
                 : "memory");
}

// Scalar grid-stride fallback for any residual tail (unused: 6291456 % 8 == 0).
__global__ void deq_st_tail(const float* __restrict__ x,
                            const float* __restrict__ lam_ptr,
                            float* __restrict__ out, int start, int n) {
    const float lam = *lam_ptr;
    for (int i = start + blockIdx.x * blockDim.x + threadIdx.x; i < n;
         i += gridDim.x * blockDim.x) {
        float v = x[i];
        out[i] = copysignf(fmaxf(fabsf(v) - lam, 0.0f), v);
    }
}

extern "C" void kernel_launch(void* const* d_in, const int* in_sizes, int n_in,
                              void* d_out, int out_size) {
    const float* x0  = (const float*)d_in[0];
    const float* lam = (const float*)d_in[2];   // d_in[1]=rho irrelevant to fixed point
    float* out = (float*)d_out;

    int n   = in_sizes[0];
    int nv8 = n >> 3;                 // 786,432 for this shape
    int covered = nv8 << 3;

    if (nv8 > 0) {
        int blocks = (nv8 + THREADS - 1) / THREADS;   // 3072
        deq_st_v8_el<<<blocks, THREADS>>>(x0, lam, out, nv8);
    }
    if (covered < n) {
        deq_st_tail<<<148, THREADS>>>(x0, lam, out, covered, n);
    }
}

// round 14
// speedup vs baseline: 1.1115x; 1.0105x over previous
#include <cuda_runtime.h>

// DEQSolver closed form: out[i] = sign(x[i]) * max(|x[i]| - lam, 0).
//
// FINAL (R8 source; reconfirmed across 3 independent runs: ncu dur
// 9.216-9.25us, wall 9.18-10.21us within harness noise).
//
// Math: the Anderson-accelerated ISTA fixed point
//   z = S_{rho*lam}((1-rho)z + rho*x)
// has exact closed form z* = S_lam(x) for rho in (0,1], and the returned
// ista_step(z*, x) equals S_lam(x) again — the entire 40-iteration solver
// collapses to one elementwise pass. rel_err vs reference: 3.5e-8.
//
// Shape: one 256-bit load + one 256-bit store per thread (LDG.E.256 /
// STG.E.256), 3072 blocks x 256 threads, L2::evict_last on both streams.
// All implementation axes measured (width, datapath incl. TMA bulk, MLP,
// wave/block geometry, eviction policy): sane shapes tie at the ~9.2us
// environmental floor; no pipe exceeds 34% in any capture — traffic is at
// the 50MB information-theoretic minimum and the limiter is the burst
// latency/clock envelope, not a saturable resource.

constexpr int THREADS = 256;

__global__ __launch_bounds__(THREADS) void deq_st_v8_el(
    const float* __restrict__ x,
    const float* __restrict__ lam_ptr,
    float* __restrict__ out,
    int nv8)
{
    int i = blockIdx.x * blockDim.x + threadIdx.x;
    if (i >= nv8) return;
    const float lam = *lam_ptr;

    const float* p = x   + (size_t)i * 8;
    float*       q = out + (size_t)i * 8;

    unsigned int b0, b1, b2, b3, b4, b5, b6, b7;
    asm volatile("ld.global.L2::evict_last.v8.b32 "
                 "{%0,%1,%2,%3,%4,%5,%6,%7}, [%8];"
                 : "=r"(b0), "=r"(b1), "=r"(b2), "=r"(b3),
                   "=r"(b4), "=r"(b5), "=r"(b6), "=r"(b7)
                 : "l"(p));

    float a0 = __int_as_float(b0), a1 = __int_as_float(b1);
    float a2 = __int_as_float(b2), a3 = __int_as_float(b3);
    float a4 = __int_as_float(b4), a5 = __int_as_float(b5);
    float a6 = __int_as_float(b6), a7 = __int_as_float(b7);

    float r0 = copysignf(fmaxf(fabsf(a0) - lam, 0.0f), a0);
    float r1 = copysignf(fmaxf(fabsf(a1) - lam, 0.0f), a1);
    float r2 = copysignf(fmaxf(fabsf(a2) - lam, 0.0f), a2);
    float r3 = copysignf(fmaxf(fabsf(a3) - lam, 0.0f), a3);
    float r4 = copysignf(fmaxf(fabsf(a4) - lam, 0.0f), a4);
    float r5 = copysignf(fmaxf(fabsf(a5) - lam, 0.0f), a5);
    float r6 = copysignf(fmaxf(fabsf(a6) - lam, 0.0f), a6);
    float r7 = copysignf(fmaxf(fabsf(a7) - lam, 0.0f), a7);

    asm volatile("st.global.L2::evict_last.v8.b32 "
                 "[%0], {%1,%2,%3,%4,%5,%6,%7,%8};"
                 :: "l"(q),
                    "r"(__float_as_uint(r0)), "r"(__float_as_uint(r1)),
                    "r"(__float_as_uint(r2)), "r"(__float_as_uint(r3)),
                    "r"(__float_as_uint(r4)), "r"(__float_as_uint(r5)),
                    "r"(__float_as_uint(r6)), "r"(__float_as_uint(r7))
                 : "memory");
}

// Scalar grid-stride fallback for any residual tail (unused: 6291456 % 8 == 0).
__global__ void deq_st_tail(const float* __restrict__ x,
                            const float* __restrict__ lam_ptr,
                            float* __restrict__ out, int start, int n) {
    const float lam = *lam_ptr;
    for (int i = start + blockIdx.x * blockDim.x + threadIdx.x; i < n;
         i += gridDim.x * blockDim.x) {
        float v = x[i];
        out[i] = copysignf(fmaxf(fabsf(v) - lam, 0.0f), v);
    }
}

extern "C" void kernel_launch(void* const* d_in, const int* in_sizes, int n_in,
                              void* d_out, int out_size) {
    const float* x0  = (const float*)d_in[0];
    const float* lam = (const float*)d_in[2];   // d_in[1]=rho irrelevant to fixed point
    float* out = (float*)d_out;

    int n   = in_sizes[0];
    int nv8 = n >> 3;                 // 786,432 for this shape
    int covered = nv8 << 3;

    if (nv8 > 0) {
        int blocks = (nv8 + THREADS - 1) / THREADS;   // 3072
        deq_st_v8_el<<<blocks, THREADS>>>(x0, lam, out, nv8);
    }
    if (covered < n) {
        deq_st_tail<<<148, THREADS>>>(x0, lam, out, covered, n);
    }
}